// round 2
// baseline (speedup 1.0000x reference)
#include <cuda_runtime.h>
#include <math.h>

// Problem constants
static constexpr int Bb = 4;
static constexpr int Tt = 4096;
static constexpr int Dd = 1024;
static constexpr int Ee = 8;
static constexpr int Kk = 2;
static constexpr int Cc = 1537;            // int(T*K/E*1.5)+1
static constexpr int SLOTS = Tt * Kk;      // 8192 per batch

// Scratch (device globals; no allocation allowed)
__device__ int   g_tope[Bb * Tt * Kk];   // expert id per (token, k) slot
__device__ float g_topw[Bb * Tt * Kk];   // softmax weight per slot
__device__ int   g_list[Bb * Ee * Cc];   // per-(b,e) kept slot ids (within-batch slot = t*2+k)
__device__ int   g_cnt [Bb * Ee];        // per-(b,e) kept count (<= C)

// ---------------------------------------------------------------------------
// Kernel 1: router logits + top-2 + softmax.  One warp per token.
// ---------------------------------------------------------------------------
__global__ __launch_bounds__(256) void router_kernel(const float* __restrict__ x,
                                                     const float* __restrict__ Wr) {
    __shared__ float wr_s[Ee * Dd];   // 32 KB
    int tid = threadIdx.x;
    for (int i = tid; i < Ee * Dd / 4; i += 256)
        ((float4*)wr_s)[i] = ((const float4*)Wr)[i];
    __syncthreads();

    int warp = tid >> 5, lane = tid & 31;
    int token = blockIdx.x * 8 + warp;           // global token in [0, B*T)
    const float* xrow = x + (size_t)token * Dd;

    float acc[Ee];
#pragma unroll
    for (int e = 0; e < Ee; e++) acc[e] = 0.f;

#pragma unroll
    for (int i = 0; i < Dd / 128; i++) {
        int d = i * 128 + lane * 4;
        float4 xv = *(const float4*)(xrow + d);
#pragma unroll
        for (int e = 0; e < Ee; e++) {
            float4 wv = *(const float4*)(wr_s + e * Dd + d);
            acc[e] += xv.x * wv.x + xv.y * wv.y + xv.z * wv.z + xv.w * wv.w;
        }
    }
#pragma unroll
    for (int off = 16; off > 0; off >>= 1)
#pragma unroll
        for (int e = 0; e < Ee; e++)
            acc[e] += __shfl_xor_sync(0xffffffffu, acc[e], off);

    if (lane == 0) {
        float v0 = -1e30f, v1 = -1e30f;
        int e0 = 0, e1 = 0;
#pragma unroll
        for (int e = 0; e < Ee; e++) {
            float v = acc[e];
            if (v > v0) { v1 = v0; e1 = e0; v0 = v; e0 = e; }
            else if (v > v1) { v1 = v; e1 = e; }
        }
        float ex = expf(v1 - v0);
        float w0 = 1.f / (1.f + ex);
        float w1 = ex * w0;
        g_tope[token * 2 + 0] = e0;
        g_tope[token * 2 + 1] = e1;
        g_topw[token * 2 + 0] = w0;
        g_topw[token * 2 + 1] = w1;
    }
}

// ---------------------------------------------------------------------------
// Kernel 2: per-batch capacity scan.  Reproduces the sequential (t,k)-order
// per-expert counter exactly, builds per-(b,e) kept-slot lists.
// One block per batch, 256 threads, 32 slots per thread, 8-counter scan.
// ---------------------------------------------------------------------------
__global__ __launch_bounds__(256) void scan_kernel() {
    int b = blockIdx.x;
    int tid = threadIdx.x;
    const int PER = SLOTS / 256;  // 32
    __shared__ int s_cnt[256][Ee + 1];  // +1 pad to break bank conflicts

    int base = b * SLOTS + tid * PER;
    int loc[Ee];
#pragma unroll
    for (int e = 0; e < Ee; e++) loc[e] = 0;
    for (int i = 0; i < PER; i++) loc[g_tope[base + i]]++;
#pragma unroll
    for (int e = 0; e < Ee; e++) s_cnt[tid][e] = loc[e];
    __syncthreads();

    for (int off = 1; off < 256; off <<= 1) {
        int tmp[Ee];
        if (tid >= off)
#pragma unroll
            for (int e = 0; e < Ee; e++) tmp[e] = s_cnt[tid - off][e];
        __syncthreads();
        if (tid >= off)
#pragma unroll
            for (int e = 0; e < Ee; e++) s_cnt[tid][e] += tmp[e];
        __syncthreads();
    }

    int offv[Ee];
#pragma unroll
    for (int e = 0; e < Ee; e++) offv[e] = (tid == 0) ? 0 : s_cnt[tid - 1][e];

    for (int i = 0; i < PER; i++) {
        int slot = tid * PER + i;
        int e = g_tope[b * SLOTS + slot];
        int p = offv[e]++;
        if (p < Cc) g_list[(b * Ee + e) * Cc + p] = slot;
    }
    if (tid == 255) {
#pragma unroll
        for (int e = 0; e < Ee; e++) {
            int c = s_cnt[255][e];
            g_cnt[b * Ee + e] = c < Cc ? c : Cc;
        }
    }
}

// ---------------------------------------------------------------------------
// Kernel 3: grouped GEMM with gathered A rows + fused weighted atomic combine.
// 128x128x8 fp32 tiling, 256 threads, 8x8 microtile.
// ---------------------------------------------------------------------------
static constexpr int BM = 128;
static constexpr int BN = 128;
static constexpr int BK = 8;

__global__ __launch_bounds__(256) void moe_gemm_kernel(const float* __restrict__ x,
                                                       const float* __restrict__ We,
                                                       float* __restrict__ out) {
    int be = blockIdx.z;
    int b = be >> 3, e = be & 7;
    int cnt = g_cnt[be];
    int m0 = blockIdx.y * BM;
    if (m0 >= cnt) return;
    int rows = cnt - m0; if (rows > BM) rows = BM;
    int n0 = blockIdx.x * BN;

    __shared__ float As[BK][BM];
    __shared__ float Bs[BK][BN];
    __shared__ int   toks[BM];
    __shared__ float wts [BM];

    int tid = threadIdx.x;
    if (tid < BM) {
        if (tid < rows) {
            int slot = g_list[be * Cc + m0 + tid];
            toks[tid] = slot >> 1;
            wts [tid] = g_topw[b * SLOTS + slot];
        } else {
            toks[tid] = 0;
            wts [tid] = 0.f;
        }
    }
    __syncthreads();

    const float* xb = x + (size_t)b * Tt * Dd;
    const float* Wb = We + (size_t)e * Dd * Dd;

    // A-tile load mapping: 256 threads load 128 rows x 8 k (one float4 each)
    int a_row = tid >> 1;
    int a_k   = (tid & 1) * 4;
    bool a_valid = (a_row < rows);
    const float* a_ptr = xb + (size_t)toks[a_row] * Dd + a_k;

    // B-tile load mapping: 8 k-rows x 128 cols (one float4 each)
    int bk = tid >> 5;
    int bf = (tid & 31) * 4;
    const float* b_ptr = Wb + (size_t)bk * Dd + n0 + bf;

    int mg = tid >> 4;   // 0..15 -> row group
    int ng = tid & 15;   // 0..15 -> col group

    float acc[8][8];
#pragma unroll
    for (int i = 0; i < 8; i++)
#pragma unroll
        for (int j = 0; j < 8; j++) acc[i][j] = 0.f;

    for (int kk = 0; kk < Dd; kk += BK) {
        float4 av = a_valid ? *(const float4*)(a_ptr + kk)
                            : make_float4(0.f, 0.f, 0.f, 0.f);
        float4 bv = *(const float4*)(b_ptr + (size_t)kk * Dd);

        As[a_k + 0][a_row] = av.x;
        As[a_k + 1][a_row] = av.y;
        As[a_k + 2][a_row] = av.z;
        As[a_k + 3][a_row] = av.w;
        *(float4*)(&Bs[bk][bf]) = bv;
        __syncthreads();

#pragma unroll
        for (int k = 0; k < BK; k++) {
            float afr[8], bfr[8];
            *(float4*)(afr)     = *(const float4*)(&As[k][mg * 8]);
            *(float4*)(afr + 4) = *(const float4*)(&As[k][mg * 8 + 4]);
            *(float4*)(bfr)     = *(const float4*)(&Bs[k][ng * 8]);
            *(float4*)(bfr + 4) = *(const float4*)(&Bs[k][ng * 8 + 4]);
#pragma unroll
            for (int i = 0; i < 8; i++)
#pragma unroll
                for (int j = 0; j < 8; j++)
                    acc[i][j] += afr[i] * bfr[j];
        }
        __syncthreads();
    }

    // Epilogue: weighted atomic combine into out[b, tok, :]
#pragma unroll
    for (int i = 0; i < 8; i++) {
        int r = mg * 8 + i;
        if (r < rows) {
            int tok  = toks[r];
            float w  = wts[r];
            float* orow = out + (size_t)b * Tt * Dd + (size_t)tok * Dd + n0 + ng * 8;
#pragma unroll
            for (int j = 0; j < 8; j++)
                atomicAdd(orow + j, w * acc[i][j]);
        }
    }
}

// ---------------------------------------------------------------------------
extern "C" void kernel_launch(void* const* d_in, const int* in_sizes, int n_in,
                              void* d_out, int out_size) {
    const float* x  = (const float*)d_in[0];
    const float* Wr = (const float*)d_in[1];
    const float* We = (const float*)d_in[2];
    float* out = (float*)d_out;

    cudaMemsetAsync(out, 0, (size_t)out_size * sizeof(float));
    router_kernel<<<Bb * Tt / 8, 256>>>(x, Wr);
    scan_kernel<<<Bb, 256>>>();
    dim3 grid(Dd / BN, (Cc + BM - 1) / BM, Bb * Ee);
    moe_gemm_kernel<<<grid, 256>>>(x, We, out);
}

// round 11
// speedup vs baseline: 2.4328x; 2.4328x over previous
#include <cuda_runtime.h>
#include <math.h>
#include <stdint.h>

// Problem constants
static constexpr int Bb = 4;
static constexpr int Tt = 4096;
static constexpr int Dd = 1024;
static constexpr int Ee = 8;
static constexpr int Cc = 1537;            // int(T*K/E*1.5)+1
static constexpr int SLOTS = Tt * 2;       // 8192 per batch

// Scratch (device globals; no allocation allowed)
__device__ int   g_tope[Bb * SLOTS];
__device__ float g_topw[Bb * SLOTS];
__device__ int   g_keep[Bb * SLOTS];
__device__ int   g_list[Bb * Ee * Cc];
__device__ int   g_cnt [Bb * Ee];
__device__ float g_xr  [Bb * Tt * Dd];            // tf32-rounded x (64 MB)
__device__ float g_WeT [Ee * Dd * Dd];            // transposed+rounded We (32 MB)
__device__ float g_Y   [(size_t)Bb * SLOTS * Dd]; // expert outputs per slot (128 MB)

__device__ __forceinline__ float rna_tf32(float v) {
    float r; asm("cvt.rna.tf32.f32 %0, %1;" : "=f"(r) : "f"(v)); return r;
}
__device__ __forceinline__ uint32_t s2u(const void* p) {
    uint32_t a;
    asm("{ .reg .u64 t; cvta.to.shared.u64 t, %1; cvt.u32.u64 %0, t; }" : "=r"(a) : "l"(p));
    return a;
}

// ---------------------------------------------------------------------------
// Kernel 1: router logits + top-2 softmax; also writes tf32-rounded x copy.
// ---------------------------------------------------------------------------
__global__ __launch_bounds__(256) void router_kernel(const float* __restrict__ x,
                                                     const float* __restrict__ Wr) {
    __shared__ float wr_s[Ee * Dd];
    int tid = threadIdx.x;
    for (int i = tid; i < Ee * Dd / 4; i += 256)
        ((float4*)wr_s)[i] = ((const float4*)Wr)[i];
    __syncthreads();

    int warp = tid >> 5, lane = tid & 31;
    int token = blockIdx.x * 8 + warp;
    const float* xrow = x + (size_t)token * Dd;
    float* xrr = g_xr + (size_t)token * Dd;

    float acc[Ee];
#pragma unroll
    for (int e = 0; e < Ee; e++) acc[e] = 0.f;

#pragma unroll
    for (int i = 0; i < Dd / 128; i++) {
        int d = i * 128 + lane * 4;
        float4 xv = *(const float4*)(xrow + d);
#pragma unroll
        for (int e = 0; e < Ee; e++) {
            float4 wv = *(const float4*)(wr_s + e * Dd + d);
            acc[e] += xv.x * wv.x + xv.y * wv.y + xv.z * wv.z + xv.w * wv.w;
        }
        float4 rv;
        rv.x = rna_tf32(xv.x); rv.y = rna_tf32(xv.y);
        rv.z = rna_tf32(xv.z); rv.w = rna_tf32(xv.w);
        *(float4*)(xrr + d) = rv;
    }
#pragma unroll
    for (int off = 16; off > 0; off >>= 1)
#pragma unroll
        for (int e = 0; e < Ee; e++)
            acc[e] += __shfl_xor_sync(0xffffffffu, acc[e], off);

    if (lane == 0) {
        float v0 = -1e30f, v1 = -1e30f;
        int e0 = 0, e1 = 0;
#pragma unroll
        for (int e = 0; e < Ee; e++) {
            float v = acc[e];
            if (v > v0) { v1 = v0; e1 = e0; v0 = v; e0 = e; }
            else if (v > v1) { v1 = v; e1 = e; }
        }
        float ex = expf(v1 - v0);
        float w0 = 1.f / (1.f + ex);
        g_tope[token * 2 + 0] = e0;
        g_tope[token * 2 + 1] = e1;
        g_topw[token * 2 + 0] = w0;
        g_topw[token * 2 + 1] = ex * w0;
    }
}

// ---------------------------------------------------------------------------
// Kernel 2: per-batch capacity scan (sequential (t,k)-order counter semantics)
// ---------------------------------------------------------------------------
__global__ __launch_bounds__(256) void scan_kernel() {
    int b = blockIdx.x;
    int tid = threadIdx.x;
    const int PER = SLOTS / 256;  // 32
    __shared__ int s_cnt[256][Ee + 1];

    int base = b * SLOTS + tid * PER;
    int loc[Ee];
#pragma unroll
    for (int e = 0; e < Ee; e++) loc[e] = 0;
    for (int i = 0; i < PER; i++) loc[g_tope[base + i]]++;
#pragma unroll
    for (int e = 0; e < Ee; e++) s_cnt[tid][e] = loc[e];
    __syncthreads();

    for (int off = 1; off < 256; off <<= 1) {
        int tmp[Ee];
        if (tid >= off)
#pragma unroll
            for (int e = 0; e < Ee; e++) tmp[e] = s_cnt[tid - off][e];
        __syncthreads();
        if (tid >= off)
#pragma unroll
            for (int e = 0; e < Ee; e++) s_cnt[tid][e] += tmp[e];
        __syncthreads();
    }

    int offv[Ee];
#pragma unroll
    for (int e = 0; e < Ee; e++) offv[e] = (tid == 0) ? 0 : s_cnt[tid - 1][e];

    for (int i = 0; i < PER; i++) {
        int slot = tid * PER + i;
        int e = g_tope[b * SLOTS + slot];
        int p = offv[e]++;
        int keep = p < Cc;
        g_keep[b * SLOTS + slot] = keep;
        if (keep) g_list[(b * Ee + e) * Cc + p] = slot;
    }
    if (tid == 255) {
#pragma unroll
        for (int e = 0; e < Ee; e++) {
            int c = s_cnt[255][e];
            g_cnt[b * Ee + e] = c < Cc ? c : Cc;
        }
    }
}

// ---------------------------------------------------------------------------
// Kernel 3: transpose + tf32-round We -> g_WeT[e][n][k]
// ---------------------------------------------------------------------------
__global__ __launch_bounds__(256) void transpose_kernel(const float* __restrict__ We) {
    __shared__ float ts[32][33];
    int e = blockIdx.z;
    int bx = blockIdx.x, by = blockIdx.y;      // f-tile (n), d-tile (k)
    int tx = threadIdx.x, ty = threadIdx.y;    // 32, 8
    const float* src = We + ((size_t)e * Dd + by * 32) * Dd + bx * 32;
#pragma unroll
    for (int j = 0; j < 4; j++)
        ts[ty + j * 8][tx] = src[(size_t)(ty + j * 8) * Dd + tx];
    __syncthreads();
    float* dst = g_WeT + ((size_t)e * Dd + bx * 32) * Dd + by * 32;
#pragma unroll
    for (int j = 0; j < 4; j++)
        dst[(size_t)(ty + j * 8) * Dd + tx] = rna_tf32(ts[tx][ty + j * 8]);
}

// ---------------------------------------------------------------------------
// Kernel 4: grouped tf32 GEMM via mma.sync.m16n8k8 (HMMA), BM=128 BN=256 BK=32,
// 3-stage cp.async pipeline, ldmatrix (b16 x4 trick = 1 tf32/thread/row).
// 8 warps: 2 (m) x 4 (n), warp tile 64x64. Writes raw expert rows to g_Y.
// ---------------------------------------------------------------------------
static constexpr int STAGES    = 3;
static constexpr int STG_BYTES = 49152;     // A 16KB + B 32KB
static constexpr int SMEM_HDR  = 2048;
static constexpr int SMEM_TOT  = SMEM_HDR + STAGES * STG_BYTES;  // 149504

__device__ __forceinline__ void ldsm_x4(uint32_t* r, uint32_t addr) {
    asm volatile("ldmatrix.sync.aligned.m8n8.x4.shared.b16 {%0,%1,%2,%3}, [%4];"
                 : "=r"(r[0]), "=r"(r[1]), "=r"(r[2]), "=r"(r[3]) : "r"(addr));
}
__device__ __forceinline__ void mma_tf32(float* d, const uint32_t* a,
                                         uint32_t b0, uint32_t b1) {
    asm volatile(
        "mma.sync.aligned.m16n8k8.row.col.f32.tf32.tf32.f32 "
        "{%0,%1,%2,%3}, {%4,%5,%6,%7}, {%8,%9}, {%0,%1,%2,%3};"
        : "+f"(d[0]), "+f"(d[1]), "+f"(d[2]), "+f"(d[3])
        : "r"(a[0]), "r"(a[1]), "r"(a[2]), "r"(a[3]), "r"(b0), "r"(b1));
}

__global__ __launch_bounds__(256, 1) void moe_gemm_mma() {
    int be = blockIdx.z, b = be >> 3, e = be & 7;
    int cnt = g_cnt[be];
    int m0 = blockIdx.y * 128;
    if (m0 >= cnt) return;
    int rows = cnt - m0; if (rows > 128) rows = 128;
    int n0 = blockIdx.x * 256;

    extern __shared__ char smem[];
    uint32_t sb = s2u(smem);
    int tid = threadIdx.x, wid = tid >> 5, lane = tid & 31;

    int* s_slot = (int*)smem;
    int* s_tok  = (int*)(smem + 512);
    if (tid < 128) {
        int slot = (tid < rows) ? g_list[be * Cc + m0 + tid] : -1;
        s_slot[tid] = slot;
        s_tok[tid]  = (slot >= 0) ? (slot >> 1) : 0;
    }
    __syncthreads();

    const float* Ab = g_xr + (size_t)b * Tt * Dd;
    const float* Bp = g_WeT + ((size_t)e * Dd + n0) * Dd;

    // cp.async mapping. A: thread -> (row=tid/2, 4 chunks from c0=(tid&1)*4).
    // B: thread -> full row tid (8 chunks). Swizzle: chunk ^= (row & 7).
    int a_row = tid >> 1, a_c0 = (tid & 1) * 4;
    const float* a_g = Ab + (size_t)s_tok[a_row] * Dd + a_c0 * 4;
    const float* b_g = Bp + (size_t)tid * Dd;
    uint32_t a_dst[4], b_dst[8];
#pragma unroll
    for (int i = 0; i < 4; i++) {
        int c = a_c0 + i;
        a_dst[i] = sb + SMEM_HDR + a_row * 128 + ((c ^ (a_row & 7)) << 4);
    }
#pragma unroll
    for (int c = 0; c < 8; c++)
        b_dst[c] = sb + SMEM_HDR + 16384 + tid * 128 + ((c ^ (tid & 7)) << 4);

#define LOAD_STAGE(it_)                                                       \
    {                                                                         \
        uint32_t so_ = ((it_) % STAGES) * STG_BYTES;                          \
        int kk_ = (it_) * 32;                                                 \
        _Pragma("unroll")                                                     \
        for (int i = 0; i < 4; i++)                                           \
            asm volatile("cp.async.cg.shared.global [%0], [%1], 16;"          \
                         :: "r"(a_dst[i] + so_), "l"(a_g + kk_ + i * 4)       \
                         : "memory");                                         \
        _Pragma("unroll")                                                     \
        for (int c = 0; c < 8; c++)                                           \
            asm volatile("cp.async.cg.shared.global [%0], [%1], 16;"          \
                         :: "r"(b_dst[c] + so_), "l"(b_g + kk_ + c * 4)       \
                         : "memory");                                         \
        asm volatile("cp.async.commit_group;" ::: "memory");                  \
    }

    int m_off = (wid & 1) * 64, n_off = (wid >> 1) * 64;
    int lr = lane & 7, lhi = (lane >> 3) & 1, lc = lane >> 4;

    float acc[4][8][4];
#pragma unroll
    for (int f = 0; f < 4; f++)
#pragma unroll
        for (int j = 0; j < 8; j++)
#pragma unroll
            for (int q = 0; q < 4; q++) acc[f][j][q] = 0.f;

    LOAD_STAGE(0);
    LOAD_STAGE(1);

    for (int it = 0; it < 32; it++) {
        asm volatile("cp.async.wait_group 1;" ::: "memory");
        __syncthreads();
        if (it + 2 < 32) LOAD_STAGE(it + 2);

        uint32_t Abase = sb + SMEM_HDR + (it % STAGES) * STG_BYTES;
        uint32_t Bbase = Abase + 16384;
#pragma unroll
        for (int ks = 0; ks < 4; ks++) {
            int chunk = 2 * ks + lc;
            uint32_t af[4][4], bw[4][4];
#pragma unroll
            for (int f = 0; f < 4; f++) {
                int row = m_off + f * 16 + lhi * 8 + lr;
                ldsm_x4(af[f], Abase + row * 128 + ((chunk ^ (row & 7)) << 4));
            }
#pragma unroll
            for (int j2 = 0; j2 < 4; j2++) {
                int row = n_off + j2 * 16 + lhi * 8 + lr;
                ldsm_x4(bw[j2], Bbase + row * 128 + ((chunk ^ (row & 7)) << 4));
            }
#pragma unroll
            for (int f = 0; f < 4; f++)
#pragma unroll
                for (int j2 = 0; j2 < 4; j2++) {
                    mma_tf32(acc[f][j2 * 2 + 0], af[f], bw[j2][0], bw[j2][2]);
                    mma_tf32(acc[f][j2 * 2 + 1], af[f], bw[j2][1], bw[j2][3]);
                }
        }
        __syncthreads();
    }

    // Epilogue: scatter to g_Y rows by slot. D frag: d0,d1 -> (row t/4, col 2c),
    // d2,d3 -> (row t/4+8).
    int erow = lane >> 2, ecol = (lane & 3) * 2;
#pragma unroll
    for (int f = 0; f < 4; f++) {
        int r0 = m_off + f * 16 + erow;
        int slot0 = s_slot[r0];
        int slot1 = s_slot[r0 + 8];
        float* y0 = g_Y + ((size_t)b * SLOTS + (slot0 >= 0 ? slot0 : 0)) * Dd + n0;
        float* y1 = g_Y + ((size_t)b * SLOTS + (slot1 >= 0 ? slot1 : 0)) * Dd + n0;
#pragma unroll
        for (int j = 0; j < 8; j++) {
            int col = n_off + j * 8 + ecol;
            if (slot0 >= 0)
                *(float2*)(y0 + col) = make_float2(acc[f][j][0], acc[f][j][1]);
            if (slot1 >= 0)
                *(float2*)(y1 + col) = make_float2(acc[f][j][2], acc[f][j][3]);
        }
    }
}

// ---------------------------------------------------------------------------
// Kernel 5: weighted combine  out[b,t,:] = w0*Y[b,2t] + w1*Y[b,2t+1]
// ---------------------------------------------------------------------------
__global__ __launch_bounds__(256) void combine_kernel(float* __restrict__ out) {
    int idx = blockIdx.x * 256 + threadIdx.x;   // float4 index
    int token = idx >> 8;
    int d4 = idx & 255;
    int b = token >> 12;
    int sbase = b * SLOTS + ((token & 4095) << 1);
    float w0 = g_topw[sbase], w1 = g_topw[sbase + 1];
    int k0 = g_keep[sbase], k1 = g_keep[sbase + 1];
    const float4* Y4 = (const float4*)g_Y;
    float4 acc = make_float4(0.f, 0.f, 0.f, 0.f);
    if (k0) {
        float4 v = Y4[(size_t)sbase * 256 + d4];
        acc.x = w0 * v.x; acc.y = w0 * v.y; acc.z = w0 * v.z; acc.w = w0 * v.w;
    }
    if (k1) {
        float4 v = Y4[(size_t)(sbase + 1) * 256 + d4];
        acc.x += w1 * v.x; acc.y += w1 * v.y; acc.z += w1 * v.z; acc.w += w1 * v.w;
    }
    ((float4*)out)[(size_t)token * 256 + d4] = acc;
}

// ---------------------------------------------------------------------------
extern "C" void kernel_launch(void* const* d_in, const int* in_sizes, int n_in,
                              void* d_out, int out_size) {
    const float* x  = (const float*)d_in[0];
    const float* Wr = (const float*)d_in[1];
    const float* We = (const float*)d_in[2];
    float* out = (float*)d_out;

    cudaFuncSetAttribute(moe_gemm_mma, cudaFuncAttributeMaxDynamicSharedMemorySize, SMEM_TOT);

    router_kernel<<<Bb * Tt / 8, 256>>>(x, Wr);
    scan_kernel<<<Bb, 256>>>();
    transpose_kernel<<<dim3(32, 32, 8), dim3(32, 8)>>>(We);
    moe_gemm_mma<<<dim3(4, 13, 32), 256, SMEM_TOT>>>();
    combine_kernel<<<(Bb * Tt * Dd / 4) / 256, 256>>>(out);
}

// round 12
// speedup vs baseline: 2.9804x; 1.2251x over previous
#include <cuda_runtime.h>
#include <math.h>
#include <stdint.h>

// Problem constants
static constexpr int Bb = 4;
static constexpr int Tt = 4096;
static constexpr int Dd = 1024;
static constexpr int Ee = 8;
static constexpr int Cc = 1537;            // int(T*K/E*1.5)+1
static constexpr int SLOTS = Tt * 2;       // 8192 per batch

// Scratch (device globals; no allocation allowed)
__device__ int   g_tope[Bb * SLOTS];
__device__ float g_topw[Bb * SLOTS];
__device__ int   g_keep[Bb * SLOTS];
__device__ int   g_list[Bb * Ee * Cc];
__device__ int   g_cnt [Bb * Ee];
__device__ float g_xr  [Bb * Tt * Dd];            // tf32-rounded x (64 MB)
__device__ float g_WeT [Ee * Dd * Dd];            // transposed+rounded We (32 MB)
__device__ float g_Y   [(size_t)Bb * SLOTS * Dd]; // expert outputs per slot (128 MB)

__device__ __forceinline__ float rna_tf32(float v) {
    float r; asm("cvt.rna.tf32.f32 %0, %1;" : "=f"(r) : "f"(v)); return r;
}
__device__ __forceinline__ uint32_t s2u(const void* p) {
    uint32_t a;
    asm("{ .reg .u64 t; cvta.to.shared.u64 t, %1; cvt.u32.u64 %0, t; }" : "=r"(a) : "l"(p));
    return a;
}

// ---------------------------------------------------------------------------
// Kernel 1: router logits + top-2 softmax; also writes tf32-rounded x copy.
// ---------------------------------------------------------------------------
__global__ __launch_bounds__(256) void router_kernel(const float* __restrict__ x,
                                                     const float* __restrict__ Wr) {
    __shared__ float wr_s[Ee * Dd];
    int tid = threadIdx.x;
    for (int i = tid; i < Ee * Dd / 4; i += 256)
        ((float4*)wr_s)[i] = ((const float4*)Wr)[i];
    __syncthreads();

    int warp = tid >> 5, lane = tid & 31;
    int token = blockIdx.x * 8 + warp;
    const float* xrow = x + (size_t)token * Dd;
    float* xrr = g_xr + (size_t)token * Dd;

    float acc[Ee];
#pragma unroll
    for (int e = 0; e < Ee; e++) acc[e] = 0.f;

#pragma unroll
    for (int i = 0; i < Dd / 128; i++) {
        int d = i * 128 + lane * 4;
        float4 xv = *(const float4*)(xrow + d);
#pragma unroll
        for (int e = 0; e < Ee; e++) {
            float4 wv = *(const float4*)(wr_s + e * Dd + d);
            acc[e] += xv.x * wv.x + xv.y * wv.y + xv.z * wv.z + xv.w * wv.w;
        }
        float4 rv;
        rv.x = rna_tf32(xv.x); rv.y = rna_tf32(xv.y);
        rv.z = rna_tf32(xv.z); rv.w = rna_tf32(xv.w);
        *(float4*)(xrr + d) = rv;
    }
#pragma unroll
    for (int off = 16; off > 0; off >>= 1)
#pragma unroll
        for (int e = 0; e < Ee; e++)
            acc[e] += __shfl_xor_sync(0xffffffffu, acc[e], off);

    if (lane == 0) {
        float v0 = -1e30f, v1 = -1e30f;
        int e0 = 0, e1 = 0;
#pragma unroll
        for (int e = 0; e < Ee; e++) {
            float v = acc[e];
            if (v > v0) { v1 = v0; e1 = e0; v0 = v; e0 = e; }
            else if (v > v1) { v1 = v; e1 = e; }
        }
        float ex = expf(v1 - v0);
        float w0 = 1.f / (1.f + ex);
        g_tope[token * 2 + 0] = e0;
        g_tope[token * 2 + 1] = e1;
        g_topw[token * 2 + 0] = w0;
        g_topw[token * 2 + 1] = ex * w0;
    }
}

// ---------------------------------------------------------------------------
// Kernel 2: per-batch capacity scan (sequential (t,k)-order counter semantics)
// ---------------------------------------------------------------------------
__global__ __launch_bounds__(256) void scan_kernel() {
    int b = blockIdx.x;
    int tid = threadIdx.x;
    const int PER = SLOTS / 256;  // 32
    __shared__ int s_cnt[256][Ee + 1];

    int base = b * SLOTS + tid * PER;
    int loc[Ee];
#pragma unroll
    for (int e = 0; e < Ee; e++) loc[e] = 0;
    for (int i = 0; i < PER; i++) loc[g_tope[base + i]]++;
#pragma unroll
    for (int e = 0; e < Ee; e++) s_cnt[tid][e] = loc[e];
    __syncthreads();

    for (int off = 1; off < 256; off <<= 1) {
        int tmp[Ee];
        if (tid >= off)
#pragma unroll
            for (int e = 0; e < Ee; e++) tmp[e] = s_cnt[tid - off][e];
        __syncthreads();
        if (tid >= off)
#pragma unroll
            for (int e = 0; e < Ee; e++) s_cnt[tid][e] += tmp[e];
        __syncthreads();
    }

    int offv[Ee];
#pragma unroll
    for (int e = 0; e < Ee; e++) offv[e] = (tid == 0) ? 0 : s_cnt[tid - 1][e];

    for (int i = 0; i < PER; i++) {
        int slot = tid * PER + i;
        int e = g_tope[b * SLOTS + slot];
        int p = offv[e]++;
        int keep = p < Cc;
        g_keep[b * SLOTS + slot] = keep;
        if (keep) g_list[(b * Ee + e) * Cc + p] = slot;
    }
    if (tid == 255) {
#pragma unroll
        for (int e = 0; e < Ee; e++) {
            int c = s_cnt[255][e];
            g_cnt[b * Ee + e] = c < Cc ? c : Cc;
        }
    }
}

// ---------------------------------------------------------------------------
// Kernel 3: transpose + tf32-round We -> g_WeT[e][n][k]
// ---------------------------------------------------------------------------
__global__ __launch_bounds__(256) void transpose_kernel(const float* __restrict__ We) {
    __shared__ float ts[32][33];
    int e = blockIdx.z;
    int bx = blockIdx.x, by = blockIdx.y;      // f-tile (n), d-tile (k)
    int tx = threadIdx.x, ty = threadIdx.y;    // 32, 8
    const float* src = We + ((size_t)e * Dd + by * 32) * Dd + bx * 32;
#pragma unroll
    for (int j = 0; j < 4; j++)
        ts[ty + j * 8][tx] = src[(size_t)(ty + j * 8) * Dd + tx];
    __syncthreads();
    float* dst = g_WeT + ((size_t)e * Dd + bx * 32) * Dd + by * 32;
#pragma unroll
    for (int j = 0; j < 4; j++)
        dst[(size_t)(ty + j * 8) * Dd + tx] = rna_tf32(ts[tx][ty + j * 8]);
}

// ---------------------------------------------------------------------------
// Kernel 4: grouped tf32 GEMM via mma.sync.m16n8k8, BM=128 BN=128 BK=32,
// 3-stage cp.async pipeline, 2 CTAs/SM (96KB smem, <=128 regs).
// 8 warps: 2 (m) x 4 (n), warp tile 64x32. Writes raw expert rows to g_Y.
// ---------------------------------------------------------------------------
static constexpr int STAGES    = 3;
static constexpr int STG_BYTES = 32768;     // A 16KB + B 16KB
static constexpr int SMEM_HDR  = 2048;
static constexpr int SMEM_TOT  = SMEM_HDR + STAGES * STG_BYTES;  // 100352

__device__ __forceinline__ void ldsm_x4(uint32_t* r, uint32_t addr) {
    asm volatile("ldmatrix.sync.aligned.m8n8.x4.shared.b16 {%0,%1,%2,%3}, [%4];"
                 : "=r"(r[0]), "=r"(r[1]), "=r"(r[2]), "=r"(r[3]) : "r"(addr));
}
__device__ __forceinline__ void mma_tf32(float* d, const uint32_t* a,
                                         uint32_t b0, uint32_t b1) {
    asm volatile(
        "mma.sync.aligned.m16n8k8.row.col.f32.tf32.tf32.f32 "
        "{%0,%1,%2,%3}, {%4,%5,%6,%7}, {%8,%9}, {%0,%1,%2,%3};"
        : "+f"(d[0]), "+f"(d[1]), "+f"(d[2]), "+f"(d[3])
        : "r"(a[0]), "r"(a[1]), "r"(a[2]), "r"(a[3]), "r"(b0), "r"(b1));
}

__global__ __launch_bounds__(256, 2) void moe_gemm_mma() {
    int be = blockIdx.z, b = be >> 3, e = be & 7;
    int cnt = g_cnt[be];
    int m0 = blockIdx.y * 128;
    if (m0 >= cnt) return;
    int rows = cnt - m0; if (rows > 128) rows = 128;
    int n0 = blockIdx.x * 128;

    extern __shared__ char smem[];
    uint32_t sb = s2u(smem);
    int tid = threadIdx.x, wid = tid >> 5, lane = tid & 31;

    int* s_slot = (int*)smem;
    int* s_tok  = (int*)(smem + 512);
    if (tid < 128) {
        int slot = (tid < rows) ? g_list[be * Cc + m0 + tid] : -1;
        s_slot[tid] = slot;
        s_tok[tid]  = (slot >= 0) ? (slot >> 1) : 0;
    }
    __syncthreads();

    const float* Ab = g_xr + (size_t)b * Tt * Dd;
    const float* Bp = g_WeT + ((size_t)e * Dd + n0) * Dd;

    // cp.async mapping, identical for A and B tiles (each 128 rows x 32 floats):
    // thread -> (row=tid/2, 4 chunks from c0=(tid&1)*4). Swizzle: chunk ^= row&7.
    int a_row = tid >> 1, a_c0 = (tid & 1) * 4;
    const float* a_g = Ab + (size_t)s_tok[a_row] * Dd + a_c0 * 4;
    const float* b_g = Bp + (size_t)a_row * Dd + a_c0 * 4;
    uint32_t a_dst[4], b_dst[4];
#pragma unroll
    for (int i = 0; i < 4; i++) {
        int c = a_c0 + i;
        uint32_t off = a_row * 128 + ((c ^ (a_row & 7)) << 4);
        a_dst[i] = sb + SMEM_HDR + off;
        b_dst[i] = sb + SMEM_HDR + 16384 + off;
    }

#define LOAD_STAGE(it_)                                                       \
    {                                                                         \
        uint32_t so_ = ((it_) % STAGES) * STG_BYTES;                          \
        int kk_ = (it_) * 32;                                                 \
        _Pragma("unroll")                                                     \
        for (int i = 0; i < 4; i++)                                           \
            asm volatile("cp.async.cg.shared.global [%0], [%1], 16;"          \
                         :: "r"(a_dst[i] + so_), "l"(a_g + kk_ + i * 4)       \
                         : "memory");                                         \
        _Pragma("unroll")                                                     \
        for (int i = 0; i < 4; i++)                                           \
            asm volatile("cp.async.cg.shared.global [%0], [%1], 16;"          \
                         :: "r"(b_dst[i] + so_), "l"(b_g + kk_ + i * 4)       \
                         : "memory");                                         \
        asm volatile("cp.async.commit_group;" ::: "memory");                  \
    }

    int m_off = (wid & 1) * 64, n_off = (wid >> 1) * 32;
    int lr = lane & 7, lhi = (lane >> 3) & 1, lc = lane >> 4;

    float acc[4][4][4];
#pragma unroll
    for (int f = 0; f < 4; f++)
#pragma unroll
        for (int j = 0; j < 4; j++)
#pragma unroll
            for (int q = 0; q < 4; q++) acc[f][j][q] = 0.f;

    LOAD_STAGE(0);
    LOAD_STAGE(1);

    for (int it = 0; it < 32; it++) {
        asm volatile("cp.async.wait_group 1;" ::: "memory");
        __syncthreads();
        if (it + 2 < 32) LOAD_STAGE(it + 2);

        uint32_t Abase = sb + SMEM_HDR + (it % STAGES) * STG_BYTES;
        uint32_t Bbase = Abase + 16384;
#pragma unroll
        for (int ks = 0; ks < 4; ks++) {
            int chunk = 2 * ks + lc;
            uint32_t af[4][4], bw[2][4];
#pragma unroll
            for (int f = 0; f < 4; f++) {
                int row = m_off + f * 16 + lhi * 8 + lr;
                ldsm_x4(af[f], Abase + row * 128 + ((chunk ^ (row & 7)) << 4));
            }
#pragma unroll
            for (int j2 = 0; j2 < 2; j2++) {
                int row = n_off + j2 * 16 + lhi * 8 + lr;
                ldsm_x4(bw[j2], Bbase + row * 128 + ((chunk ^ (row & 7)) << 4));
            }
#pragma unroll
            for (int f = 0; f < 4; f++)
#pragma unroll
                for (int j2 = 0; j2 < 2; j2++) {
                    mma_tf32(acc[f][j2 * 2 + 0], af[f], bw[j2][0], bw[j2][2]);
                    mma_tf32(acc[f][j2 * 2 + 1], af[f], bw[j2][1], bw[j2][3]);
                }
        }
        __syncthreads();
    }

    // Epilogue: scatter to g_Y rows by slot. D frag: d0,d1 -> (row t/4, col 2c),
    // d2,d3 -> (row t/4+8).
    int erow = lane >> 2, ecol = (lane & 3) * 2;
#pragma unroll
    for (int f = 0; f < 4; f++) {
        int r0 = m_off + f * 16 + erow;
        int slot0 = s_slot[r0];
        int slot1 = s_slot[r0 + 8];
        float* y0 = g_Y + ((size_t)b * SLOTS + (slot0 >= 0 ? slot0 : 0)) * Dd + n0;
        float* y1 = g_Y + ((size_t)b * SLOTS + (slot1 >= 0 ? slot1 : 0)) * Dd + n0;
#pragma unroll
        for (int j = 0; j < 4; j++) {
            int col = n_off + j * 8 + ecol;
            if (slot0 >= 0)
                *(float2*)(y0 + col) = make_float2(acc[f][j][0], acc[f][j][1]);
            if (slot1 >= 0)
                *(float2*)(y1 + col) = make_float2(acc[f][j][2], acc[f][j][3]);
        }
    }
}

// ---------------------------------------------------------------------------
// Kernel 5: weighted combine  out[b,t,:] = w0*Y[b,2t] + w1*Y[b,2t+1]
// ---------------------------------------------------------------------------
__global__ __launch_bounds__(256) void combine_kernel(float* __restrict__ out) {
    int idx = blockIdx.x * 256 + threadIdx.x;   // float4 index
    int token = idx >> 8;
    int d4 = idx & 255;
    int b = token >> 12;
    int sbase = b * SLOTS + ((token & 4095) << 1);
    float w0 = g_topw[sbase], w1 = g_topw[sbase + 1];
    int k0 = g_keep[sbase], k1 = g_keep[sbase + 1];
    const float4* Y4 = (const float4*)g_Y;
    float4 acc = make_float4(0.f, 0.f, 0.f, 0.f);
    if (k0) {
        float4 v = Y4[(size_t)sbase * 256 + d4];
        acc.x = w0 * v.x; acc.y = w0 * v.y; acc.z = w0 * v.z; acc.w = w0 * v.w;
    }
    if (k1) {
        float4 v = Y4[(size_t)(sbase + 1) * 256 + d4];
        acc.x += w1 * v.x; acc.y += w1 * v.y; acc.z += w1 * v.z; acc.w += w1 * v.w;
    }
    ((float4*)out)[(size_t)token * 256 + d4] = acc;
}

// ---------------------------------------------------------------------------
extern "C" void kernel_launch(void* const* d_in, const int* in_sizes, int n_in,
                              void* d_out, int out_size) {
    const float* x  = (const float*)d_in[0];
    const float* Wr = (const float*)d_in[1];
    const float* We = (const float*)d_in[2];
    float* out = (float*)d_out;

    cudaFuncSetAttribute(moe_gemm_mma, cudaFuncAttributeMaxDynamicSharedMemorySize, SMEM_TOT);

    router_kernel<<<Bb * Tt / 8, 256>>>(x, Wr);
    scan_kernel<<<Bb, 256>>>();
    transpose_kernel<<<dim3(32, 32, 8), dim3(32, 8)>>>(We);
    moe_gemm_mma<<<dim3(8, 13, 32), 256, SMEM_TOT>>>();
    combine_kernel<<<(Bb * Tt * Dd / 4) / 256, 256>>>(out);
}